// round 8
// baseline (speedup 1.0000x reference)
#include <cuda_runtime.h>
#include <cuda_bf16.h>
#include <cstdint>
#include <cstddef>

// ---------------- problem constants ----------------
#define DD   768
#define MTOK 16
#define SS   1024
#define BB   16
#define TT   (SS + MTOK)   // 1040
#define TP   1152          // padded kv len (array stride)
#define KPV  1088          // K extent for P*Vt GEMM (17 x 64)
#define NQ   (BB * SS)     // 16384
#define NKV  (BB * TT)     // 16640
#define SCALE 0.036084391824351615f

// ---------------- scratch (device globals) ----------------
// int8 two-level operands + per-row scales
__device__ __align__(256) int8_t g_kv1[(size_t)NKV * DD];
__device__ __align__(256) int8_t g_kv2[(size_t)NKV * DD];
__device__ __align__(256) float  g_skv[NKV];
__device__ __align__(256) int8_t g_w1[4][(size_t)DD * DD];
__device__ __align__(256) int8_t g_w2[4][(size_t)DD * DD];
__device__ __align__(256) float  g_sw[4 * DD];
__device__ __align__(256) int8_t g_q1[(size_t)NQ * DD];
__device__ __align__(256) int8_t g_q2[(size_t)NQ * DD];
__device__ __align__(256) float  g_sq[NQ];
__device__ __align__(256) int8_t g_k1[(size_t)NKV * DD];
__device__ __align__(256) int8_t g_k2[(size_t)NKV * DD];
__device__ __align__(256) float  g_sk[NKV];
__device__ __align__(256) int8_t g_vt1[(size_t)BB * DD * TP];
__device__ __align__(256) int8_t g_vt2[(size_t)BB * DD * TP];
__device__ __align__(256) float  g_svt[BB * DD];
__device__ __align__(256) int8_t g_p1[(size_t)BB * SS * TP];
__device__ __align__(256) int8_t g_p2[(size_t)BB * SS * TP];
__device__ __align__(256) float  g_sp[NQ];
__device__ __align__(256) int8_t g_h1[(size_t)NQ * DD];
__device__ __align__(256) int8_t g_h2[(size_t)NQ * DD];
__device__ __align__(256) float  g_sh[NQ];
// f32 intermediates
__device__ __align__(256) float g_qf [(size_t)NQ * DD];
__device__ __align__(256) float g_kf [(size_t)NKV * DD];
__device__ __align__(256) float g_vtf[(size_t)BB * DD * TP];
__device__ __align__(256) float g_sc [(size_t)BB * SS * TP];
__device__ __align__(256) float g_hf [(size_t)NQ * DD];

// ---------------- helpers ----------------
__device__ __forceinline__ uint32_t smem_u32(const void* p) {
    uint32_t a;
    asm("{ .reg .u64 t; cvta.to.shared.u64 t, %1; cvt.u32.u64 %0, t; }" : "=r"(a) : "l"(p));
    return a;
}
__device__ __forceinline__ void cp16(uint32_t dst, const void* src) {
    asm volatile("cp.async.cg.shared.global [%0], [%1], 16;" :: "r"(dst), "l"(src));
}
__device__ __forceinline__ void cp_commit() {
    asm volatile("cp.async.commit_group;" ::: "memory");
}
template <int N>
__device__ __forceinline__ void cp_wait() {
    asm volatile("cp.async.wait_group %0;" :: "n"(N) : "memory");
}
__device__ __forceinline__ void ldm4(uint32_t* r, uint32_t addr) {
    asm volatile("ldmatrix.sync.aligned.m8n8.x4.shared.b16 {%0,%1,%2,%3},[%4];"
                 : "=r"(r[0]), "=r"(r[1]), "=r"(r[2]), "=r"(r[3]) : "r"(addr));
}
__device__ __forceinline__ void mma_s8(int* c, const uint32_t* a, const uint32_t* b) {
    asm volatile("mma.sync.aligned.m16n8k32.row.col.s32.s8.s8.s32 "
                 "{%0,%1,%2,%3},{%4,%5,%6,%7},{%8,%9},{%0,%1,%2,%3};"
                 : "+r"(c[0]), "+r"(c[1]), "+r"(c[2]), "+r"(c[3])
                 : "r"(a[0]), "r"(a[1]), "r"(a[2]), "r"(a[3]), "r"(b[0]), "r"(b[1]));
}

// ---------------- quantization (warp per row, 2 passes) ----------------
__device__ __forceinline__ void quant_row(const float4* src, int8_t* q1, int8_t* q2,
                                          float* scale_out, int cols, int lane)
{
    const int nj = cols >> 7;      // float4 groups per lane
    float mx = 0.0f;
    for (int j = 0; j < nj; j++) {
        float4 v = src[lane + 32 * j];
        mx = fmaxf(mx, fmaxf(fmaxf(fabsf(v.x), fabsf(v.y)), fmaxf(fabsf(v.z), fabsf(v.w))));
    }
    #pragma unroll
    for (int o = 16; o > 0; o >>= 1) mx = fmaxf(mx, __shfl_xor_sync(0xFFFFFFFFu, mx, o));
    const float inv = mx > 0.0f ? 127.0f / mx : 0.0f;
    for (int j = 0; j < nj; j++) {
        float4 v = src[lane + 32 * j];
        float f[4] = {v.x, v.y, v.z, v.w};
        char c1[4], c2[4];
        #pragma unroll
        for (int e = 0; e < 4; e++) {
            float t  = f[e] * inv;
            float t1 = rintf(t);
            c1[e] = (char)__float2int_rn(t);
            c2[e] = (char)__float2int_rn((t - t1) * 128.0f);
        }
        *(char4*)(q1 + (lane + 32 * j) * 4) = make_char4(c1[0], c1[1], c1[2], c1[3]);
        *(char4*)(q2 + (lane + 32 * j) * 4) = make_char4(c2[0], c2[1], c2[2], c2[3]);
    }
    if (lane == 0) *scale_out = mx * (1.0f / 127.0f);
}

__global__ void quant_rows(const float* __restrict__ src, int8_t* __restrict__ q1,
                           int8_t* __restrict__ q2, float* __restrict__ sc, int cols)
{
    int row  = blockIdx.x * 8 + (threadIdx.x >> 5);
    int lane = threadIdx.x & 31;
    quant_row((const float4*)(src + (size_t)row * cols),
              q1 + (size_t)row * cols, q2 + (size_t)row * cols, sc + row, cols, lane);
}

__global__ void kv_quant(const float* __restrict__ x, const float* __restrict__ mem)
{
    int row  = blockIdx.x * 8 + (threadIdx.x >> 5);
    int lane = threadIdx.x & 31;
    int b = row / TT, t = row % TT;
    const float* srcp = (t < SS) ? (x + (size_t)(b * SS + t) * DD)
                                 : (mem + (size_t)(t - SS) * DD);
    quant_row((const float4*)srcp,
              g_kv1 + (size_t)row * DD, g_kv2 + (size_t)row * DD, g_skv + row, DD, lane);
}

__global__ void w_quant(const float* __restrict__ w0, const float* __restrict__ w1,
                        const float* __restrict__ w2, const float* __restrict__ w3)
{
    int row  = blockIdx.x * 8 + (threadIdx.x >> 5);   // 0..3071
    int lane = threadIdx.x & 31;
    int sel = row / DD, r = row % DD;
    const float* src = (sel == 0) ? w0 : (sel == 1) ? w1 : (sel == 2) ? w2 : w3;
    quant_row((const float4*)(src + (size_t)r * DD),
              g_w1[sel] + (size_t)r * DD, g_w2[sel] + (size_t)r * DD,
              g_sw + sel * DD + r, DD, lane);
}

// ---------------- int8 2-level GEMM ----------------
// C[m,n] = alpha * sa[m] sb[n] * (A1B1 + (A1B2 + A2B1)/128) (+bias)(+mask) -> f32
// Block 128x128, BK=64 int8, 256 threads (8 warps 4x2), warp tile 32x64.
// SMEM row = 128B = [lvl1 64B | lvl2 64B], XOR-swizzled 16B units. 3-stage cp.async.

#define AST 16384
#define BST 16384
#define STAGE (AST + BST)          // 32768
#define GSMEM (3 * STAGE)          // 98304

__global__ void __launch_bounds__(256, 1)
gemm_i8(const int8_t* __restrict__ A1, const int8_t* __restrict__ A2,
        const float* __restrict__ sa, long long strA, long long strSa, int ldA, int mrealA,
        const int8_t* __restrict__ B1, const int8_t* __restrict__ B2,
        const float* __restrict__ sb, long long strB, long long strSb, int ldB, int nrealB,
        int K, float alpha,
        const float* __restrict__ bias, int bias_mode,   // 0 none, 1 over N, 2 over M
        const float* __restrict__ mask, int mask_ld, int mask_n,
        float* __restrict__ Cf, long long strC, int ldC)
{
    extern __shared__ char smem[];
    const uint32_t sbm = smem_u32(smem);
    const int tid  = threadIdx.x;
    const int lane = tid & 31;
    const int warp = tid >> 5;
    const int wm = warp >> 1;          // 0..3 (32-row slabs)
    const int wn = warp & 1;           // 0..1 (64-col slabs)

    const int m0 = blockIdx.y * 128, n0 = blockIdx.x * 128;
    const int8_t* pA1 = A1 + (size_t)blockIdx.z * strA;
    const int8_t* pA2 = A2 + (size_t)blockIdx.z * strA;
    const int8_t* pB1 = B1 + (size_t)blockIdx.z * strB;
    const int8_t* pB2 = B2 + (size_t)blockIdx.z * strB;
    const float*  psa = sa + (size_t)blockIdx.z * strSa;
    const float*  psb = sb + (size_t)blockIdx.z * strSb;

    // ---- cp.async mapping: 2 threads per row, h = level ----
    const int r = tid >> 1, h = tid & 1;
    int garow = m0 + r; if (garow >= mrealA) garow = mrealA - 1;
    const int8_t* srcA = (h ? pA2 : pA1) + (size_t)garow * ldA;
    uint32_t dstA[4];
    #pragma unroll
    for (int j = 0; j < 4; j++)
        dstA[j] = sbm + (uint32_t)r * 128u + (uint32_t)((((h << 2) + j) ^ (r & 7)) * 16);

    int gbrow = n0 + r; if (gbrow >= nrealB) gbrow = nrealB - 1;
    const int8_t* srcB = (h ? pB2 : pB1) + (size_t)gbrow * ldB;
    uint32_t dstB[4];
    #pragma unroll
    for (int j = 0; j < 4; j++)
        dstB[j] = sbm + AST + (uint32_t)r * 128u + (uint32_t)((((h << 2) + j) ^ (r & 7)) * 16);

    const int nchunk = K >> 6;

    auto prefetch = [&](int c, int stg) {
        const uint32_t so = (uint32_t)stg * STAGE;
        const int k0 = c << 6;
        #pragma unroll
        for (int j = 0; j < 4; j++) cp16(dstA[j] + so, srcA + k0 + j * 16);
        #pragma unroll
        for (int j = 0; j < 4; j++) cp16(dstB[j] + so, srcB + k0 + j * 16);
    };

    int acc1[2][8][4], accm[2][8][4];
    #pragma unroll
    for (int i = 0; i < 2; i++)
        #pragma unroll
        for (int j = 0; j < 8; j++)
            #pragma unroll
            for (int q = 0; q < 4; q++) { acc1[i][j][q] = 0; accm[i][j][q] = 0; }

    const uint32_t band  = (uint32_t)(lane & 7);
    const uint32_t a_sel = (uint32_t)(lane >> 4);
    uint32_t arowt[2];
    #pragma unroll
    for (int mt = 0; mt < 2; mt++)
        arowt[mt] = (uint32_t)(wm * 32 + mt * 16 + (lane & 15)) * 128u;
    const uint32_t b_off = (uint32_t)(((lane >> 4) & 1) * 8 + (lane & 7));
    const uint32_t b_hi  = (uint32_t)((lane >> 3) & 1);

    prefetch(0, 0); cp_commit();
    if (nchunk > 1) prefetch(1, 1);
    cp_commit();

    for (int c = 0; c < nchunk; c++) {
        cp_wait<1>();
        __syncthreads();
        if (c + 2 < nchunk) prefetch(c + 2, (c + 2) % 3);
        cp_commit();

        const uint32_t Ab = sbm + (uint32_t)(c % 3) * STAGE;
        const uint32_t Bb = Ab + AST;

        #pragma unroll
        for (int ks = 0; ks < 2; ks++) {
            uint32_t a1f[2][4], a2f[2][4];
            const uint32_t ca = (uint32_t)(ks * 2) + a_sel;
            #pragma unroll
            for (int mt = 0; mt < 2; mt++) {
                ldm4(a1f[mt], Ab + arowt[mt] + ((ca    ) ^ band) * 16);
                ldm4(a2f[mt], Ab + arowt[mt] + ((ca + 4) ^ band) * 16);
            }
            const uint32_t cb = (uint32_t)(ks * 2) + b_hi;
            #pragma unroll
            for (int ntp = 0; ntp < 4; ntp++) {
                uint32_t b1f[4], b2f[4];
                const uint32_t brt = (uint32_t)(wn * 64 + ntp * 16) * 128u + b_off * 128u;
                ldm4(b1f, Bb + brt + ((cb    ) ^ band) * 16);
                ldm4(b2f, Bb + brt + ((cb + 4) ^ band) * 16);
                #pragma unroll
                for (int mt = 0; mt < 2; mt++) {
                    mma_s8(acc1[mt][ntp * 2    ], a1f[mt], b1f);
                    mma_s8(acc1[mt][ntp * 2 + 1], a1f[mt], b1f + 2);
                }
                #pragma unroll
                for (int mt = 0; mt < 2; mt++) {
                    mma_s8(accm[mt][ntp * 2    ], a1f[mt], b2f);
                    mma_s8(accm[mt][ntp * 2 + 1], a1f[mt], b2f + 2);
                }
                #pragma unroll
                for (int mt = 0; mt < 2; mt++) {
                    mma_s8(accm[mt][ntp * 2    ], a2f[mt], b1f);
                    mma_s8(accm[mt][ntp * 2 + 1], a2f[mt], b1f + 2);
                }
            }
        }
    }

    // ---- epilogue: dequant + bias/mask -> f32 ----
    float* pC = Cf + (size_t)blockIdx.z * strC;

    #pragma unroll
    for (int mt = 0; mt < 2; mt++) {
        const int row0 = m0 + wm * 32 + mt * 16 + (lane >> 2);
        #pragma unroll
        for (int nt = 0; nt < 8; nt++) {
            const int col = n0 + wn * 64 + nt * 8 + (lane & 3) * 2;
            const int c0 = col < nrealB ? col : nrealB - 1;
            const int c1 = (col + 1) < nrealB ? (col + 1) : nrealB - 1;
            const float sb0 = psb[c0], sb1 = psb[c1];
            #pragma unroll
            for (int half = 0; half < 2; half++) {
                const int row = row0 + half * 8;
                const float fa = alpha * psa[row];
                float v0 = fa * sb0 * ((float)acc1[mt][nt][half * 2    ]
                                       + (float)accm[mt][nt][half * 2    ] * 0.0078125f);
                float v1 = fa * sb1 * ((float)acc1[mt][nt][half * 2 + 1]
                                       + (float)accm[mt][nt][half * 2 + 1] * 0.0078125f);
                if (bias_mode == 1) {
                    float2 bv = *(const float2*)(bias + col);
                    v0 += bv.x; v1 += bv.y;
                } else if (bias_mode == 2) {
                    float bm = bias[row];
                    v0 += bm; v1 += bm;
                }
                if (mask && col < mask_n) {
                    float2 mv = *(const float2*)(mask + (size_t)row * mask_ld + col);
                    v0 += mv.x; v1 += mv.y;
                }
                float2 ov; ov.x = v0; ov.y = v1;
                *(float2*)(pC + (size_t)row * ldC + col) = ov;
            }
        }
    }
}

// ---------------- softmax with direct int8 quantization of P ----------------
__device__ __forceinline__ float wmaxr(float v) {
    #pragma unroll
    for (int o = 16; o > 0; o >>= 1) v = fmaxf(v, __shfl_xor_sync(0xFFFFFFFFu, v, o));
    return v;
}
__device__ __forceinline__ float wsumr(float v) {
    #pragma unroll
    for (int o = 16; o > 0; o >>= 1) v += __shfl_xor_sync(0xFFFFFFFFu, v, o);
    return v;
}

__global__ void __launch_bounds__(256)
softmax_quant(const float* __restrict__ SC, int8_t* __restrict__ P1,
              int8_t* __restrict__ P2, float* __restrict__ SP)
{
    const size_t base = (size_t)blockIdx.x * TP;
    const float* rrow = SC + base;
    const int tid = threadIdx.x, lane = tid & 31, warp = tid >> 5;
    __shared__ float red[8];

    float v[5];
    float mx = -1e30f;
    #pragma unroll
    for (int i = 0; i < 5; i++) {
        int t = tid + i * 256;
        if (t < TT) { float x = rrow[t]; v[i] = x; mx = fmaxf(mx, x); }
        else v[i] = -1e30f;
    }
    mx = wmaxr(mx);
    if (lane == 0) red[warp] = mx;
    __syncthreads();
    if (warp == 0) {
        float x = (lane < 8) ? red[lane] : -1e30f;
        x = wmaxr(x);
        if (lane == 0) red[0] = x;
    }
    __syncthreads();
    mx = red[0];
    __syncthreads();

    float sum = 0.0f;
    #pragma unroll
    for (int i = 0; i < 5; i++) {
        int t = tid + i * 256;
        if (t < TT) { float e = expf(v[i] - mx); v[i] = e; sum += e; }
    }
    sum = wsumr(sum);
    if (lane == 0) red[warp] = sum;
    __syncthreads();
    if (warp == 0) {
        float x = (lane < 8) ? red[lane] : 0.0f;
        x = wsumr(x);
        if (lane == 0) red[0] = x;
    }
    __syncthreads();
    const float inv = 1.0f / red[0];

    // p = v*inv, scale = inv/127 -> P1 = rint(127*v), P2 = rint((127v - P1)*128)
    #pragma unroll
    for (int i = 0; i < 5; i++) {
        int t = tid + i * 256;
        if (t < TT) {
            float tq  = 127.0f * v[i];
            float t1  = rintf(tq);
            P1[base + t] = (int8_t)__float2int_rn(tq);
            P2[base + t] = (int8_t)__float2int_rn((tq - t1) * 128.0f);
        } else if (t < TP) {
            P1[base + t] = 0;
            P2[base + t] = 0;
        }
    }
    if (tid == 0) SP[blockIdx.x] = inv * (1.0f / 127.0f);
}

// ---------------- launch ----------------
extern "C" void kernel_launch(void* const* d_in, const int* in_sizes, int n_in,
                              void* d_out, int out_size)
{
    const float* x    = (const float*)d_in[0];
    const float* mask = (const float*)d_in[1];
    const float* mem  = (const float*)d_in[2];
    const float* wq   = (const float*)d_in[3];
    const float* bq   = (const float*)d_in[4];
    const float* wk   = (const float*)d_in[5];
    const float* bk   = (const float*)d_in[6];
    const float* wv   = (const float*)d_in[7];
    const float* bv   = (const float*)d_in[8];
    const float* wo   = (const float*)d_in[9];
    const float* bo   = (const float*)d_in[10];
    float* out = (float*)d_out;

    int8_t *kv1, *kv2, *q1, *q2, *k1, *k2, *vt1, *vt2, *p1, *p2, *h1, *h2;
    int8_t (*w1)[(size_t)DD * DD];
    int8_t (*w2)[(size_t)DD * DD];
    float *skv, *sw, *sq, *sk, *svt, *sp, *sh;
    float *qf, *kf, *vtf, *sc, *hf;
    cudaGetSymbolAddress((void**)&kv1, g_kv1);  cudaGetSymbolAddress((void**)&kv2, g_kv2);
    cudaGetSymbolAddress((void**)&skv, g_skv);
    cudaGetSymbolAddress((void**)&w1,  g_w1);   cudaGetSymbolAddress((void**)&w2,  g_w2);
    cudaGetSymbolAddress((void**)&sw,  g_sw);
    cudaGetSymbolAddress((void**)&q1,  g_q1);   cudaGetSymbolAddress((void**)&q2,  g_q2);
    cudaGetSymbolAddress((void**)&sq,  g_sq);
    cudaGetSymbolAddress((void**)&k1,  g_k1);   cudaGetSymbolAddress((void**)&k2,  g_k2);
    cudaGetSymbolAddress((void**)&sk,  g_sk);
    cudaGetSymbolAddress((void**)&vt1, g_vt1);  cudaGetSymbolAddress((void**)&vt2, g_vt2);
    cudaGetSymbolAddress((void**)&svt, g_svt);
    cudaGetSymbolAddress((void**)&p1,  g_p1);   cudaGetSymbolAddress((void**)&p2,  g_p2);
    cudaGetSymbolAddress((void**)&sp,  g_sp);
    cudaGetSymbolAddress((void**)&h1,  g_h1);   cudaGetSymbolAddress((void**)&h2,  g_h2);
    cudaGetSymbolAddress((void**)&sh,  g_sh);
    cudaGetSymbolAddress((void**)&qf,  g_qf);
    cudaGetSymbolAddress((void**)&kf,  g_kf);
    cudaGetSymbolAddress((void**)&vtf, g_vtf);
    cudaGetSymbolAddress((void**)&sc,  g_sc);
    cudaGetSymbolAddress((void**)&hf,  g_hf);

    cudaFuncSetAttribute(gemm_i8, cudaFuncAttributeMaxDynamicSharedMemorySize, GSMEM);

    // 0: build + quantize kv (concat x | memory)
    kv_quant<<<NKV / 8, 256>>>(x, mem);
    // 1: quantize all weights
    w_quant<<<(4 * DD) / 8, 256>>>(wq, wk, wv, wo);

    // 2: Qf = x * wq^T + bq  (batched; A rows skip memory tokens)
    gemm_i8<<<dim3(DD / 128, SS / 128, BB), 256, GSMEM>>>(
        kv1, kv2, skv, (long long)TT * DD, TT, DD, SS,
        w1[0], w2[0], sw + 0 * DD, 0, 0, DD, DD,
        DD, 1.0f, bq, 1, nullptr, 0, 0,
        qf, (long long)SS * DD, DD);
    // 3: quantize Q rows
    quant_rows<<<NQ / 8, 256>>>(qf, q1, q2, sq, DD);
    // 4: Kf = kv * wk^T + bk
    gemm_i8<<<dim3(DD / 128, NKV / 128, 1), 256, GSMEM>>>(
        kv1, kv2, skv, 0, 0, DD, NKV,
        w1[1], w2[1], sw + 1 * DD, 0, 0, DD, DD,
        DD, 1.0f, bk, 1, nullptr, 0, 0,
        kf, 0, DD);
    // 5: Vtf[b] = wv * kv[b]^T + bv(rows)    [768 x TP]   <- ncu capture target
    gemm_i8<<<dim3(TP / 128, DD / 128, BB), 256, GSMEM>>>(
        w1[2], w2[2], sw + 2 * DD, 0, 0, DD, DD,
        kv1, kv2, skv, (long long)TT * DD, TT, DD, TT,
        DD, 1.0f, bv, 2, nullptr, 0, 0,
        vtf, (long long)DD * TP, TP);
    // 6,7: quantize K rows and Vt rows
    quant_rows<<<NKV / 8, 256>>>(kf, k1, k2, sk, DD);
    quant_rows<<<(BB * DD) / 8, 256>>>(vtf, vt1, vt2, svt, TP);

    // 8: scores[b] = SCALE * Q[b] K[b]^T + mask -> f32
    gemm_i8<<<dim3(TP / 128, SS / 128, BB), 256, GSMEM>>>(
        q1, q2, sq, (long long)SS * DD, SS, DD, SS,
        k1, k2, sk, (long long)TT * DD, TT, DD, TT,
        DD, SCALE, nullptr, 0, mask, TT, TT,
        sc, (long long)SS * TP, TP);

    // 9: softmax -> quantized P (pad zeroed)
    softmax_quant<<<NQ, 256>>>(sc, p1, p2, sp);

    // 10: Hf[b] = P[b] * Vt[b]^T   (K = 1088, pads are exact zeros)
    gemm_i8<<<dim3(DD / 128, SS / 128, BB), 256, GSMEM>>>(
        p1, p2, sp, (long long)SS * TP, SS, TP, SS,
        vt1, vt2, svt, (long long)DD * TP, DD, TP, DD,
        KPV, 1.0f, nullptr, 0, nullptr, 0, 0,
        hf, (long long)SS * DD, DD);
    // 11: quantize H rows
    quant_rows<<<NQ / 8, 256>>>(hf, h1, h2, sh, DD);

    // 12: out = H * wo^T + bo -> f32 d_out
    gemm_i8<<<dim3(DD / 128, NQ / 128, 1), 256, GSMEM>>>(
        h1, h2, sh, 0, 0, DD, NQ,
        w1[3], w2[3], sw + 3 * DD, 0, 0, DD, DD,
        DD, 1.0f, bo, 1, nullptr, 0, 0,
        out, 0, DD);
}

// round 9
// speedup vs baseline: 2.4016x; 2.4016x over previous
#include <cuda_runtime.h>
#include <cuda_bf16.h>
#include <cstdint>
#include <cstddef>

// ---------------- problem constants ----------------
#define DD   768
#define MTOK 16
#define SS   1024
#define BB   16
#define TT   (SS + MTOK)   // 1040
#define TP   1152          // padded kv len (array stride)
#define KPV  1088          // K extent for P*Vt GEMM (17 x 64)
#define NQ   (BB * SS)     // 16384
#define NKV  (BB * TT)     // 16640
#define SCALE 0.036084391824351615f

// ---------------- scratch (device globals) ----------------
__device__ __align__(256) __nv_bfloat16 g_kvhi[(size_t)NKV * DD];
__device__ __align__(256) __nv_bfloat16 g_kvlo[(size_t)NKV * DD];
__device__ __align__(256) __nv_bfloat16 g_qhi [(size_t)NQ  * DD];
__device__ __align__(256) __nv_bfloat16 g_qlo [(size_t)NQ  * DD];
__device__ __align__(256) __nv_bfloat16 g_khi [(size_t)NKV * DD];
__device__ __align__(256) __nv_bfloat16 g_klo [(size_t)NKV * DD];
__device__ __align__(256) __nv_bfloat16 g_vthi[(size_t)BB * DD * TP];
__device__ __align__(256) __nv_bfloat16 g_vtlo[(size_t)BB * DD * TP];
__device__ __align__(256) float         g_sc  [(size_t)BB * SS * TP];
__device__ __align__(256) __nv_bfloat16 g_phi [(size_t)BB * SS * TP];
__device__ __align__(256) __nv_bfloat16 g_plo [(size_t)BB * SS * TP];
__device__ __align__(256) __nv_bfloat16 g_hhi [(size_t)NQ  * DD];
__device__ __align__(256) __nv_bfloat16 g_hlo [(size_t)NQ  * DD];
__device__ __align__(256) __nv_bfloat16 g_whi [4][(size_t)DD * DD];
__device__ __align__(256) __nv_bfloat16 g_wlo [4][(size_t)DD * DD];

// ---------------- helpers ----------------
__device__ __forceinline__ void bsplit(float f, __nv_bfloat16& h, __nv_bfloat16& l) {
    h = __float2bfloat16(f);
    l = __float2bfloat16(f - __bfloat162float(h));
}
__device__ __forceinline__ uint32_t smem_u32(const void* p) {
    uint32_t a;
    asm("{ .reg .u64 t; cvta.to.shared.u64 t, %1; cvt.u32.u64 %0, t; }" : "=r"(a) : "l"(p));
    return a;
}
__device__ __forceinline__ void cp16(uint32_t dst, const void* src) {
    asm volatile("cp.async.cg.shared.global [%0], [%1], 16;" :: "r"(dst), "l"(src));
}
__device__ __forceinline__ void cp_commit() {
    asm volatile("cp.async.commit_group;" ::: "memory");
}
template <int N>
__device__ __forceinline__ void cp_wait() {
    asm volatile("cp.async.wait_group %0;" :: "n"(N) : "memory");
}
__device__ __forceinline__ void ldm4(uint32_t* r, uint32_t addr) {
    asm volatile("ldmatrix.sync.aligned.m8n8.x4.shared.b16 {%0,%1,%2,%3},[%4];"
                 : "=r"(r[0]), "=r"(r[1]), "=r"(r[2]), "=r"(r[3]) : "r"(addr));
}
__device__ __forceinline__ void mma16816(float* c, const uint32_t* a, const uint32_t* b) {
    asm volatile("mma.sync.aligned.m16n8k16.row.col.f32.bf16.bf16.f32 "
                 "{%0,%1,%2,%3},{%4,%5,%6,%7},{%8,%9},{%0,%1,%2,%3};"
                 : "+f"(c[0]), "+f"(c[1]), "+f"(c[2]), "+f"(c[3])
                 : "r"(a[0]), "r"(a[1]), "r"(a[2]), "r"(a[3]), "r"(b[0]), "r"(b[1]));
}

// ---------------- elementwise prep ----------------
__global__ void build_kv(const float4* __restrict__ x, const float4* __restrict__ mem) {
    const int n4 = NKV * (DD / 4);
    int i = blockIdx.x * 256 + threadIdx.x;
    if (i >= n4) return;
    int d4  = i % (DD / 4);
    int row = i / (DD / 4);
    int b = row / TT, t = row % TT;
    float4 v = (t < SS) ? x[(size_t)(b * SS + t) * (DD / 4) + d4]
                        : mem[(size_t)(t - SS) * (DD / 4) + d4];
    union { __nv_bfloat16 bb[4]; uint2 u; } H, L;
    bsplit(v.x, H.bb[0], L.bb[0]);
    bsplit(v.y, H.bb[1], L.bb[1]);
    bsplit(v.z, H.bb[2], L.bb[2]);
    bsplit(v.w, H.bb[3], L.bb[3]);
    ((uint2*)g_kvhi)[i] = H.u;
    ((uint2*)g_kvlo)[i] = L.u;
}

__global__ void split_all(const float4* __restrict__ w0, const float4* __restrict__ w1,
                          const float4* __restrict__ w2, const float4* __restrict__ w3) {
    const int w4 = DD * DD / 4;
    int i = blockIdx.x * 256 + threadIdx.x;
    if (i >= 4 * w4) return;
    int wsel = i / w4;
    int j    = i % w4;
    const float4* src = (wsel == 0) ? w0 : (wsel == 1) ? w1 : (wsel == 2) ? w2 : w3;
    float4 v = src[j];
    union { __nv_bfloat16 bb[4]; uint2 u; } H, L;
    bsplit(v.x, H.bb[0], L.bb[0]);
    bsplit(v.y, H.bb[1], L.bb[1]);
    bsplit(v.z, H.bb[2], L.bb[2]);
    bsplit(v.w, H.bb[3], L.bb[3]);
    ((uint2*)g_whi[wsel])[j] = H.u;
    ((uint2*)g_wlo[wsel])[j] = L.u;
}

// ---------------- HMMA split-bf16 GEMM, BK=64 ----------------
// Block 128x128, BK=64, 256 threads (8 warps, 4x2), warp tile 32x64.
// 4 matrices per stage: Ahi | Alo | Bhi | Blo, each 128 rows x 128B, XOR-8 swizzle.
// 2-stage cp.async pipeline (128KB). No register cap (avoid spills).

#define MATB  16384                // one matrix tile: 128 x 128B
#define STAGE (4 * MATB)           // 65536
#define GSMEM (2 * STAGE)          // 131072

__global__ void __launch_bounds__(256, 1)
gemm3(const __nv_bfloat16* __restrict__ Ahi, const __nv_bfloat16* __restrict__ Alo,
      long long sA, int ldA, int mrealA,
      const __nv_bfloat16* __restrict__ Bhi, const __nv_bfloat16* __restrict__ Blo,
      long long sB, int ldB, int nrealB,
      int K, float alpha,
      const float* __restrict__ bias, int bias_mode,   // 0 none, 1 over N, 2 over M
      const float* __restrict__ mask, int mask_ld, int mask_n,
      float* __restrict__ Cf, __nv_bfloat16* __restrict__ Chi, __nv_bfloat16* __restrict__ Clo,
      long long sC, int ldC)
{
    extern __shared__ char smem[];
    const uint32_t sb = smem_u32(smem);
    const int tid  = threadIdx.x;
    const int lane = tid & 31;
    const int warp = tid >> 5;
    const int wm = warp >> 1;          // 0..3 (32-row slabs)
    const int wn = warp & 1;           // 0..1 (64-col slabs)

    const int m0 = blockIdx.y * 128, n0 = blockIdx.x * 128;
    const __nv_bfloat16* pAh = Ahi + (size_t)blockIdx.z * sA;
    const __nv_bfloat16* pAl = Alo + (size_t)blockIdx.z * sA;
    const __nv_bfloat16* pBh = Bhi + (size_t)blockIdx.z * sB;
    const __nv_bfloat16* pBl = Blo + (size_t)blockIdx.z * sB;

    // ---- cp.async mapping: thread (r = tid>>1, h = tid&1) covers 64B of each 128B row ----
    const int r = tid >> 1, h = tid & 1;
    int garow = m0 + r; if (garow >= mrealA) garow = mrealA - 1;
    int gbrow = n0 + r; if (gbrow >= nrealB) gbrow = nrealB - 1;
    const __nv_bfloat16* srcAh = pAh + (size_t)garow * ldA + h * 32;
    const __nv_bfloat16* srcAl = pAl + (size_t)garow * ldA + h * 32;
    const __nv_bfloat16* srcBh = pBh + (size_t)gbrow * ldB + h * 32;
    const __nv_bfloat16* srcBl = pBl + (size_t)gbrow * ldB + h * 32;
    uint32_t dstu[4];                  // swizzled 16B-unit offsets within a row
    #pragma unroll
    for (int j = 0; j < 4; j++)
        dstu[j] = (uint32_t)r * 128u + (uint32_t)((((h << 2) + j) ^ (r & 7)) * 16);

    const int nchunk = K >> 6;

    auto prefetch = [&](int c, int stg) {
        const uint32_t so = sb + (uint32_t)stg * STAGE;
        const int k0 = c << 6;
        #pragma unroll
        for (int j = 0; j < 4; j++) cp16(so + 0 * MATB + dstu[j], srcAh + k0 + j * 8);
        #pragma unroll
        for (int j = 0; j < 4; j++) cp16(so + 1 * MATB + dstu[j], srcAl + k0 + j * 8);
        #pragma unroll
        for (int j = 0; j < 4; j++) cp16(so + 2 * MATB + dstu[j], srcBh + k0 + j * 8);
        #pragma unroll
        for (int j = 0; j < 4; j++) cp16(so + 3 * MATB + dstu[j], srcBl + k0 + j * 8);
    };

    float acc[2][8][4];
    #pragma unroll
    for (int i = 0; i < 2; i++)
        #pragma unroll
        for (int j = 0; j < 8; j++)
            #pragma unroll
            for (int q = 0; q < 4; q++) acc[i][j][q] = 0.0f;

    const uint32_t band = (uint32_t)(lane & 7);
    const uint32_t a_hi = (uint32_t)(lane >> 4);        // 0/1
    uint32_t arowt[2];
    #pragma unroll
    for (int mt = 0; mt < 2; mt++)
        arowt[mt] = (uint32_t)(wm * 32 + mt * 16 + (lane & 15)) * 128u;
    const uint32_t b_off = (uint32_t)(((lane >> 4) & 1) * 8 + (lane & 7));
    const uint32_t b_hi  = (uint32_t)((lane >> 3) & 1);

    prefetch(0, 0); cp_commit();

    for (int c = 0; c < nchunk; c++) {
        if (c + 1 < nchunk) { prefetch(c + 1, (c + 1) & 1); cp_commit(); cp_wait<1>(); }
        else                { cp_wait<0>(); }
        __syncthreads();

        const uint32_t Ab = sb + (uint32_t)(c & 1) * STAGE;
        const uint32_t Bb = Ab + 2 * MATB;

        #pragma unroll
        for (int ks = 0; ks < 4; ks++) {
            uint32_t ah[2][4], al[2][4];
            const uint32_t ua = (uint32_t)(ks * 2) + a_hi;
            #pragma unroll
            for (int mt = 0; mt < 2; mt++) {
                ldm4(ah[mt], Ab + 0 * MATB + arowt[mt] + (ua ^ band) * 16);
                ldm4(al[mt], Ab + 1 * MATB + arowt[mt] + (ua ^ band) * 16);
            }
            const uint32_t ub = (uint32_t)(ks * 2) + b_hi;
            #pragma unroll
            for (int ntp = 0; ntp < 4; ntp++) {
                uint32_t bh[4], bl[4];
                const uint32_t brt = (uint32_t)(wn * 64 + ntp * 16 + b_off) * 128u;
                ldm4(bh, Bb + 0 * MATB + brt + (ub ^ band) * 16);
                ldm4(bl, Bb + 1 * MATB + brt + (ub ^ band) * 16);
                #pragma unroll
                for (int mt = 0; mt < 2; mt++) {
                    mma16816(acc[mt][ntp * 2    ], ah[mt], bh);
                    mma16816(acc[mt][ntp * 2 + 1], ah[mt], bh + 2);
                }
                #pragma unroll
                for (int mt = 0; mt < 2; mt++) {
                    mma16816(acc[mt][ntp * 2    ], ah[mt], bl);
                    mma16816(acc[mt][ntp * 2 + 1], ah[mt], bl + 2);
                }
                #pragma unroll
                for (int mt = 0; mt < 2; mt++) {
                    mma16816(acc[mt][ntp * 2    ], al[mt], bh);
                    mma16816(acc[mt][ntp * 2 + 1], al[mt], bh + 2);
                }
            }
        }
        __syncthreads();
    }

    // ---- epilogue ----
    float* pC = Cf ? (Cf + (size_t)blockIdx.z * sC) : (float*)0;
    __nv_bfloat16* pCh = Chi ? (Chi + (size_t)blockIdx.z * sC) : (__nv_bfloat16*)0;
    __nv_bfloat16* pCl = Clo ? (Clo + (size_t)blockIdx.z * sC) : (__nv_bfloat16*)0;

    #pragma unroll
    for (int mt = 0; mt < 2; mt++) {
        const int row0 = m0 + wm * 32 + mt * 16 + (lane >> 2);
        #pragma unroll
        for (int nt = 0; nt < 8; nt++) {
            const int col = n0 + wn * 64 + nt * 8 + (lane & 3) * 2;
            #pragma unroll
            for (int half = 0; half < 2; half++) {
                const int row = row0 + half * 8;
                float v0 = acc[mt][nt][half * 2    ] * alpha;
                float v1 = acc[mt][nt][half * 2 + 1] * alpha;
                if (bias_mode == 1) {
                    float2 bv = *(const float2*)(bias + col);
                    v0 += bv.x; v1 += bv.y;
                } else if (bias_mode == 2) {
                    float bm = bias[row];
                    v0 += bm; v1 += bm;
                }
                if (mask && col < mask_n) {
                    float2 mv = *(const float2*)(mask + (size_t)row * mask_ld + col);
                    v0 += mv.x; v1 += mv.y;
                }
                if (pC) {
                    float2 ov; ov.x = v0; ov.y = v1;
                    *(float2*)(pC + (size_t)row * ldC + col) = ov;
                } else {
                    __nv_bfloat16 h0, l0, h1, l1;
                    bsplit(v0, h0, l0);
                    bsplit(v1, h1, l1);
                    union { __nv_bfloat16 bb[2]; uint32_t u; } H, L;
                    H.bb[0] = h0; H.bb[1] = h1;
                    L.bb[0] = l0; L.bb[1] = l1;
                    *(uint32_t*)(pCh + (size_t)row * ldC + col) = H.u;
                    *(uint32_t*)(pCl + (size_t)row * ldC + col) = L.u;
                }
            }
        }
    }
}

// ---------------- softmax ----------------
__device__ __forceinline__ float wmax(float v) {
    #pragma unroll
    for (int o = 16; o > 0; o >>= 1) v = fmaxf(v, __shfl_xor_sync(0xFFFFFFFFu, v, o));
    return v;
}
__device__ __forceinline__ float wsum(float v) {
    #pragma unroll
    for (int o = 16; o > 0; o >>= 1) v += __shfl_xor_sync(0xFFFFFFFFu, v, o);
    return v;
}

__global__ void __launch_bounds__(256)
softmax_split(const float* __restrict__ SC, __nv_bfloat16* __restrict__ Phi,
              __nv_bfloat16* __restrict__ Plo)
{
    const size_t base = (size_t)blockIdx.x * TP;
    const float* rrow = SC + base;
    const int tid = threadIdx.x, lane = tid & 31, warp = tid >> 5;
    __shared__ float red[8];

    float v[5];
    float mx = -1e30f;
    #pragma unroll
    for (int i = 0; i < 5; i++) {
        int t = tid + i * 256;
        if (t < TT) { float x = rrow[t]; v[i] = x; mx = fmaxf(mx, x); }
        else v[i] = -1e30f;
    }
    mx = wmax(mx);
    if (lane == 0) red[warp] = mx;
    __syncthreads();
    if (warp == 0) {
        float x = (lane < 8) ? red[lane] : -1e30f;
        x = wmax(x);
        if (lane == 0) red[0] = x;
    }
    __syncthreads();
    mx = red[0];
    __syncthreads();

    float sum = 0.0f;
    #pragma unroll
    for (int i = 0; i < 5; i++) {
        int t = tid + i * 256;
        if (t < TT) { float e = expf(v[i] - mx); v[i] = e; sum += e; }
    }
    sum = wsum(sum);
    if (lane == 0) red[warp] = sum;
    __syncthreads();
    if (warp == 0) {
        float x = (lane < 8) ? red[lane] : 0.0f;
        x = wsum(x);
        if (lane == 0) red[0] = x;
    }
    __syncthreads();
    const float inv = 1.0f / red[0];

    #pragma unroll
    for (int i = 0; i < 5; i++) {
        int t = tid + i * 256;
        if (t < TT) {
            float p = v[i] * inv;
            __nv_bfloat16 hh, ll;
            bsplit(p, hh, ll);
            Phi[base + t] = hh;
            Plo[base + t] = ll;
        } else if (t < TP) {
            Phi[base + t] = __float2bfloat16(0.0f);
            Plo[base + t] = __float2bfloat16(0.0f);
        }
    }
}

// ---------------- launch ----------------
extern "C" void kernel_launch(void* const* d_in, const int* in_sizes, int n_in,
                              void* d_out, int out_size)
{
    const float* x    = (const float*)d_in[0];
    const float* mask = (const float*)d_in[1];
    const float* mem  = (const float*)d_in[2];
    const float* wq   = (const float*)d_in[3];
    const float* bq   = (const float*)d_in[4];
    const float* wk   = (const float*)d_in[5];
    const float* bk   = (const float*)d_in[6];
    const float* wv   = (const float*)d_in[7];
    const float* bv   = (const float*)d_in[8];
    const float* wo   = (const float*)d_in[9];
    const float* bo   = (const float*)d_in[10];
    float* out = (float*)d_out;

    __nv_bfloat16 *kvhi, *kvlo, *qhi, *qlo, *khi, *klo, *vthi, *vtlo, *phi, *plo, *hhi, *hlo;
    __nv_bfloat16 (*whi)[(size_t)DD * DD];
    __nv_bfloat16 (*wlo)[(size_t)DD * DD];
    float* sc;
    cudaGetSymbolAddress((void**)&kvhi, g_kvhi);
    cudaGetSymbolAddress((void**)&kvlo, g_kvlo);
    cudaGetSymbolAddress((void**)&qhi,  g_qhi);
    cudaGetSymbolAddress((void**)&qlo,  g_qlo);
    cudaGetSymbolAddress((void**)&khi,  g_khi);
    cudaGetSymbolAddress((void**)&klo,  g_klo);
    cudaGetSymbolAddress((void**)&vthi, g_vthi);
    cudaGetSymbolAddress((void**)&vtlo, g_vtlo);
    cudaGetSymbolAddress((void**)&sc,   g_sc);
    cudaGetSymbolAddress((void**)&phi,  g_phi);
    cudaGetSymbolAddress((void**)&plo,  g_plo);
    cudaGetSymbolAddress((void**)&hhi,  g_hhi);
    cudaGetSymbolAddress((void**)&hlo,  g_hlo);
    cudaGetSymbolAddress((void**)&whi,  g_whi);
    cudaGetSymbolAddress((void**)&wlo,  g_wlo);

    cudaFuncSetAttribute(gemm3, cudaFuncAttributeMaxDynamicSharedMemorySize, GSMEM);

    // 0: concat + split kv input
    {
        int n4 = NKV * (DD / 4);
        build_kv<<<(n4 + 255) / 256, 256>>>((const float4*)x, (const float4*)mem);
    }
    // 1: split all weights
    {
        int tot = 4 * (DD * DD / 4);
        split_all<<<(tot + 255) / 256, 256>>>((const float4*)wq, (const float4*)wk,
                                              (const float4*)wv, (const float4*)wo);
    }

    // 2: Q = x * wq^T + bq  (batched; A rows skip memory tokens)
    gemm3<<<dim3(DD / 128, SS / 128, BB), 256, GSMEM>>>(
        kvhi, kvlo, (long long)TT * DD, DD, SS,
        whi[0], wlo[0], 0, DD, DD,
        DD, 1.0f, bq, 1, nullptr, 0, 0,
        nullptr, qhi, qlo, (long long)SS * DD, DD);

    // 3: K = kv * wk^T + bk
    gemm3<<<dim3(DD / 128, NKV / 128, 1), 256, GSMEM>>>(
        kvhi, kvlo, 0, DD, NKV,
        whi[1], wlo[1], 0, DD, DD,
        DD, 1.0f, bk, 1, nullptr, 0, 0,
        nullptr, khi, klo, 0, DD);

    // 4: Vt[b] = wv * kv[b]^T + bv(rows)   [768 x TP]
    gemm3<<<dim3(TP / 128, DD / 128, BB), 256, GSMEM>>>(
        whi[2], wlo[2], 0, DD, DD,
        kvhi, kvlo, (long long)TT * DD, DD, TT,
        DD, 1.0f, bv, 2, nullptr, 0, 0,
        nullptr, vthi, vtlo, (long long)DD * TP, TP);

    // 5: scores[b] = SCALE * Q[b] K[b]^T + mask -> fp32
    gemm3<<<dim3(TP / 128, SS / 128, BB), 256, GSMEM>>>(
        qhi, qlo, (long long)SS * DD, DD, SS,
        khi, klo, (long long)TT * DD, DD, TT,
        DD, SCALE, nullptr, 0, mask, TT, TT,
        sc, nullptr, nullptr, (long long)SS * TP, TP);

    // 6: softmax -> split P (pad cols zeroed)
    softmax_split<<<NQ, 256>>>(sc, phi, plo);

    // 7: H[b] = P[b] * Vt[b]^T   (K = 1088, pads are exact zeros)
    gemm3<<<dim3(DD / 128, SS / 128, BB), 256, GSMEM>>>(
        phi, plo, (long long)SS * TP, TP, SS,
        vthi, vtlo, (long long)DD * TP, TP, DD,
        KPV, 1.0f, nullptr, 0, nullptr, 0, 0,
        nullptr, hhi, hlo, (long long)SS * DD, DD);

    // 8: out = H * wo^T + bo -> fp32 d_out
    gemm3<<<dim3(DD / 128, NQ / 128, 1), 256, GSMEM>>>(
        hhi, hlo, 0, DD, NQ,
        whi[3], wlo[3], 0, DD, DD,
        DD, 1.0f, bo, 1, nullptr, 0, 0,
        out, nullptr, nullptr, 0, DD);
}

// round 10
// speedup vs baseline: 2.4037x; 1.0009x over previous
#include <cuda_runtime.h>
#include <cuda_bf16.h>
#include <cstdint>
#include <cstddef>

// ---------------- problem constants ----------------
#define DD   768
#define MTOK 16
#define SS   1024
#define BB   16
#define TT   (SS + MTOK)   // 1040
#define TP   1152          // padded kv len (array stride)
#define KPV  1088          // K extent for P*Vt GEMM (17 x 64)
#define NQ   (BB * SS)     // 16384
#define NKV  (BB * TT)     // 16640
#define SCALE 0.036084391824351615f

// ---------------- scratch (device globals) ----------------
__device__ __align__(256) __nv_bfloat16 g_kvhi[(size_t)NKV * DD];
__device__ __align__(256) __nv_bfloat16 g_kvlo[(size_t)NKV * DD];
__device__ __align__(256) __nv_bfloat16 g_qhi [(size_t)NQ  * DD];
__device__ __align__(256) __nv_bfloat16 g_qlo [(size_t)NQ  * DD];
__device__ __align__(256) __nv_bfloat16 g_khi [(size_t)NKV * DD];
__device__ __align__(256) __nv_bfloat16 g_klo [(size_t)NKV * DD];
__device__ __align__(256) __nv_bfloat16 g_vthi[(size_t)BB * DD * TP];
__device__ __align__(256) __nv_bfloat16 g_vtlo[(size_t)BB * DD * TP];
__device__ __align__(256) float         g_sc  [(size_t)BB * SS * TP];
__device__ __align__(256) __nv_bfloat16 g_phi [(size_t)BB * SS * TP];
__device__ __align__(256) __nv_bfloat16 g_plo [(size_t)BB * SS * TP];
__device__ __align__(256) __nv_bfloat16 g_hhi [(size_t)NQ  * DD];
__device__ __align__(256) __nv_bfloat16 g_hlo [(size_t)NQ  * DD];
__device__ __align__(256) __nv_bfloat16 g_whi [4][(size_t)DD * DD];
__device__ __align__(256) __nv_bfloat16 g_wlo [4][(size_t)DD * DD];

// ---------------- helpers ----------------
__device__ __forceinline__ void bsplit(float f, __nv_bfloat16& h, __nv_bfloat16& l) {
    h = __float2bfloat16(f);
    l = __float2bfloat16(f - __bfloat162float(h));
}
__device__ __forceinline__ uint32_t smem_u32(const void* p) {
    uint32_t a;
    asm("{ .reg .u64 t; cvta.to.shared.u64 t, %1; cvt.u32.u64 %0, t; }" : "=r"(a) : "l"(p));
    return a;
}
__device__ __forceinline__ void cp16(uint32_t dst, const void* src) {
    asm volatile("cp.async.cg.shared.global [%0], [%1], 16;" :: "r"(dst), "l"(src));
}
__device__ __forceinline__ void cp_commit() {
    asm volatile("cp.async.commit_group;" ::: "memory");
}
template <int N>
__device__ __forceinline__ void cp_wait() {
    asm volatile("cp.async.wait_group %0;" :: "n"(N) : "memory");
}
__device__ __forceinline__ void ldm4(uint32_t* r, uint32_t addr) {
    asm volatile("ldmatrix.sync.aligned.m8n8.x4.shared.b16 {%0,%1,%2,%3},[%4];"
                 : "=r"(r[0]), "=r"(r[1]), "=r"(r[2]), "=r"(r[3]) : "r"(addr));
}
__device__ __forceinline__ void mma16816(float* c, const uint32_t* a, const uint32_t* b) {
    asm volatile("mma.sync.aligned.m16n8k16.row.col.f32.bf16.bf16.f32 "
                 "{%0,%1,%2,%3},{%4,%5,%6,%7},{%8,%9},{%0,%1,%2,%3};"
                 : "+f"(c[0]), "+f"(c[1]), "+f"(c[2]), "+f"(c[3])
                 : "r"(a[0]), "r"(a[1]), "r"(a[2]), "r"(a[3]), "r"(b[0]), "r"(b[1]));
}

// ---------------- elementwise prep ----------------
__global__ void build_kv(const float4* __restrict__ x, const float4* __restrict__ mem) {
    const int n4 = NKV * (DD / 4);
    int i = blockIdx.x * 256 + threadIdx.x;
    if (i >= n4) return;
    int d4  = i % (DD / 4);
    int row = i / (DD / 4);
    int b = row / TT, t = row % TT;
    float4 v = (t < SS) ? x[(size_t)(b * SS + t) * (DD / 4) + d4]
                        : mem[(size_t)(t - SS) * (DD / 4) + d4];
    union { __nv_bfloat16 bb[4]; uint2 u; } H, L;
    bsplit(v.x, H.bb[0], L.bb[0]);
    bsplit(v.y, H.bb[1], L.bb[1]);
    bsplit(v.z, H.bb[2], L.bb[2]);
    bsplit(v.w, H.bb[3], L.bb[3]);
    ((uint2*)g_kvhi)[i] = H.u;
    ((uint2*)g_kvlo)[i] = L.u;
}

__global__ void split_all(const float4* __restrict__ w0, const float4* __restrict__ w1,
                          const float4* __restrict__ w2, const float4* __restrict__ w3) {
    const int w4 = DD * DD / 4;
    int i = blockIdx.x * 256 + threadIdx.x;
    if (i >= 4 * w4) return;
    int wsel = i / w4;
    int j    = i % w4;
    const float4* src = (wsel == 0) ? w0 : (wsel == 1) ? w1 : (wsel == 2) ? w2 : w3;
    float4 v = src[j];
    union { __nv_bfloat16 bb[4]; uint2 u; } H, L;
    bsplit(v.x, H.bb[0], L.bb[0]);
    bsplit(v.y, H.bb[1], L.bb[1]);
    bsplit(v.z, H.bb[2], L.bb[2]);
    bsplit(v.w, H.bb[3], L.bb[3]);
    ((uint2*)g_whi[wsel])[j] = H.u;
    ((uint2*)g_wlo[wsel])[j] = L.u;
}

// ---------------- HMMA split-bf16 GEMM, BK=64, 3-stage, frag-pipelined ----------------
// Block 128x128, 256 threads (8 warps, 4x2), warp tile 32x64.
// 4 matrices per stage: Ahi|Alo|Bhi|Blo, each 128 x 128B, XOR-8 swizzle.
// One __syncthreads per chunk; frag double-buffer hides LDSM latency.

#define MATB  16384                // one matrix tile: 128 x 128B
#define STAGE (4 * MATB)           // 65536
#define GSMEM (3 * STAGE)          // 196608

__global__ void __launch_bounds__(256, 1)
gemm3(const __nv_bfloat16* __restrict__ Ahi, const __nv_bfloat16* __restrict__ Alo,
      long long sA, int ldA, int mrealA,
      const __nv_bfloat16* __restrict__ Bhi, const __nv_bfloat16* __restrict__ Blo,
      long long sB, int ldB, int nrealB,
      int K, float alpha,
      const float* __restrict__ bias, int bias_mode,   // 0 none, 1 over N, 2 over M
      const float* __restrict__ mask, int mask_ld, int mask_n,
      float* __restrict__ Cf, __nv_bfloat16* __restrict__ Chi, __nv_bfloat16* __restrict__ Clo,
      long long sC, int ldC)
{
    extern __shared__ char smem[];
    const uint32_t sb = smem_u32(smem);
    const int tid  = threadIdx.x;
    const int lane = tid & 31;
    const int warp = tid >> 5;
    const int wm = warp >> 1;          // 0..3 (32-row slabs)
    const int wn = warp & 1;           // 0..1 (64-col slabs)

    const int m0 = blockIdx.y * 128, n0 = blockIdx.x * 128;
    const __nv_bfloat16* pAh = Ahi + (size_t)blockIdx.z * sA;
    const __nv_bfloat16* pAl = Alo + (size_t)blockIdx.z * sA;
    const __nv_bfloat16* pBh = Bhi + (size_t)blockIdx.z * sB;
    const __nv_bfloat16* pBl = Blo + (size_t)blockIdx.z * sB;

    // ---- cp.async mapping ----
    const int r = tid >> 1, h = tid & 1;
    int garow = m0 + r; if (garow >= mrealA) garow = mrealA - 1;
    int gbrow = n0 + r; if (gbrow >= nrealB) gbrow = nrealB - 1;
    const __nv_bfloat16* srcAh = pAh + (size_t)garow * ldA + h * 32;
    const __nv_bfloat16* srcAl = pAl + (size_t)garow * ldA + h * 32;
    const __nv_bfloat16* srcBh = pBh + (size_t)gbrow * ldB + h * 32;
    const __nv_bfloat16* srcBl = pBl + (size_t)gbrow * ldB + h * 32;
    uint32_t dstu[4];
    #pragma unroll
    for (int j = 0; j < 4; j++)
        dstu[j] = (uint32_t)r * 128u + (uint32_t)((((h << 2) + j) ^ (r & 7)) * 16);

    const int nchunk = K >> 6;

    auto prefetch = [&](int c, int stg) {
        const uint32_t so = sb + (uint32_t)stg * STAGE;
        const int k0 = c << 6;
        #pragma unroll
        for (int j = 0; j < 4; j++) cp16(so + 0 * MATB + dstu[j], srcAh + k0 + j * 8);
        #pragma unroll
        for (int j = 0; j < 4; j++) cp16(so + 1 * MATB + dstu[j], srcAl + k0 + j * 8);
        #pragma unroll
        for (int j = 0; j < 4; j++) cp16(so + 2 * MATB + dstu[j], srcBh + k0 + j * 8);
        #pragma unroll
        for (int j = 0; j < 4; j++) cp16(so + 3 * MATB + dstu[j], srcBl + k0 + j * 8);
    };

    float acc[2][8][4];
    #pragma unroll
    for (int i = 0; i < 2; i++)
        #pragma unroll
        for (int j = 0; j < 8; j++)
            #pragma unroll
            for (int q = 0; q < 4; q++) acc[i][j][q] = 0.0f;

    const uint32_t band = (uint32_t)(lane & 7);
    const uint32_t a_hi = (uint32_t)(lane >> 4);
    uint32_t arowt[2];
    #pragma unroll
    for (int mt = 0; mt < 2; mt++)
        arowt[mt] = (uint32_t)(wm * 32 + mt * 16 + (lane & 15)) * 128u;
    const uint32_t b_off = (uint32_t)(((lane >> 4) & 1) * 8 + (lane & 7));
    const uint32_t b_hi  = (uint32_t)((lane >> 3) & 1);

    // frag double buffers
    uint32_t fah[2][2][4], fal[2][2][4], fbh[2][4][4], fbl[2][4][4];

    prefetch(0, 0); cp_commit();
    if (nchunk > 1) prefetch(1, 1);
    cp_commit();

    for (int c = 0; c < nchunk; c++) {
        cp_wait<1>();
        __syncthreads();
        if (c + 2 < nchunk) prefetch(c + 2, (c + 2) % 3);
        cp_commit();

        const uint32_t Ab = sb + (uint32_t)(c % 3) * STAGE;
        const uint32_t Bb = Ab + 2 * MATB;

        #pragma unroll
        for (int ks = 0; ks < 4; ks++) {
            if (ks == 0) {
                // load frags for ks=0 into buffer 0
                const uint32_t ua = a_hi;          // ks*2 = 0
                #pragma unroll
                for (int mt = 0; mt < 2; mt++) {
                    ldm4(fah[0][mt], Ab + 0 * MATB + arowt[mt] + (ua ^ band) * 16);
                    ldm4(fal[0][mt], Ab + 1 * MATB + arowt[mt] + (ua ^ band) * 16);
                }
                const uint32_t ub = b_hi;
                #pragma unroll
                for (int ntp = 0; ntp < 4; ntp++) {
                    const uint32_t brt = (uint32_t)(wn * 64 + ntp * 16 + b_off) * 128u;
                    ldm4(fbh[0][ntp], Bb + 0 * MATB + brt + (ub ^ band) * 16);
                    ldm4(fbl[0][ntp], Bb + 1 * MATB + brt + (ub ^ band) * 16);
                }
            }
            if (ks < 3) {
                // load frags for ks+1 into the other buffer (hides LDSM latency under MMAs)
                const int nb = (ks + 1) & 1;
                const uint32_t ua = (uint32_t)((ks + 1) * 2) + a_hi;
                #pragma unroll
                for (int mt = 0; mt < 2; mt++) {
                    ldm4(fah[nb][mt], Ab + 0 * MATB + arowt[mt] + (ua ^ band) * 16);
                    ldm4(fal[nb][mt], Ab + 1 * MATB + arowt[mt] + (ua ^ band) * 16);
                }
                const uint32_t ub = (uint32_t)((ks + 1) * 2) + b_hi;
                #pragma unroll
                for (int ntp = 0; ntp < 4; ntp++) {
                    const uint32_t brt = (uint32_t)(wn * 64 + ntp * 16 + b_off) * 128u;
                    ldm4(fbh[nb][ntp], Bb + 0 * MATB + brt + (ub ^ band) * 16);
                    ldm4(fbl[nb][ntp], Bb + 1 * MATB + brt + (ub ^ band) * 16);
                }
            }
            // MMAs for ks from buffer ks&1
            const int cb = ks & 1;
            #pragma unroll
            for (int ntp = 0; ntp < 4; ntp++) {
                #pragma unroll
                for (int mt = 0; mt < 2; mt++) {
                    mma16816(acc[mt][ntp * 2    ], fah[cb][mt], fbh[cb][ntp]);
                    mma16816(acc[mt][ntp * 2 + 1], fah[cb][mt], fbh[cb][ntp] + 2);
                }
                #pragma unroll
                for (int mt = 0; mt < 2; mt++) {
                    mma16816(acc[mt][ntp * 2    ], fah[cb][mt], fbl[cb][ntp]);
                    mma16816(acc[mt][ntp * 2 + 1], fah[cb][mt], fbl[cb][ntp] + 2);
                }
                #pragma unroll
                for (int mt = 0; mt < 2; mt++) {
                    mma16816(acc[mt][ntp * 2    ], fal[cb][mt], fbh[cb][ntp]);
                    mma16816(acc[mt][ntp * 2 + 1], fal[cb][mt], fbh[cb][ntp] + 2);
                }
            }
        }
    }

    // ---- epilogue ----
    float* pC = Cf ? (Cf + (size_t)blockIdx.z * sC) : (float*)0;
    __nv_bfloat16* pCh = Chi ? (Chi + (size_t)blockIdx.z * sC) : (__nv_bfloat16*)0;
    __nv_bfloat16* pCl = Clo ? (Clo + (size_t)blockIdx.z * sC) : (__nv_bfloat16*)0;

    #pragma unroll
    for (int mt = 0; mt < 2; mt++) {
        const int row0 = m0 + wm * 32 + mt * 16 + (lane >> 2);
        #pragma unroll
        for (int nt = 0; nt < 8; nt++) {
            const int col = n0 + wn * 64 + nt * 8 + (lane & 3) * 2;
            #pragma unroll
            for (int half = 0; half < 2; half++) {
                const int row = row0 + half * 8;
                float v0 = acc[mt][nt][half * 2    ] * alpha;
                float v1 = acc[mt][nt][half * 2 + 1] * alpha;
                if (bias_mode == 1) {
                    float2 bv = *(const float2*)(bias + col);
                    v0 += bv.x; v1 += bv.y;
                } else if (bias_mode == 2) {
                    float bm = bias[row];
                    v0 += bm; v1 += bm;
                }
                if (mask && col < mask_n) {
                    float2 mv = *(const float2*)(mask + (size_t)row * mask_ld + col);
                    v0 += mv.x; v1 += mv.y;
                }
                if (pC) {
                    float2 ov; ov.x = v0; ov.y = v1;
                    *(float2*)(pC + (size_t)row * ldC + col) = ov;
                } else {
                    __nv_bfloat16 h0, l0, h1, l1;
                    bsplit(v0, h0, l0);
                    bsplit(v1, h1, l1);
                    union { __nv_bfloat16 bb[2]; uint32_t u; } H, L;
                    H.bb[0] = h0; H.bb[1] = h1;
                    L.bb[0] = l0; L.bb[1] = l1;
                    *(uint32_t*)(pCh + (size_t)row * ldC + col) = H.u;
                    *(uint32_t*)(pCl + (size_t)row * ldC + col) = L.u;
                }
            }
        }
    }
}

// ---------------- softmax ----------------
__device__ __forceinline__ float wmax(float v) {
    #pragma unroll
    for (int o = 16; o > 0; o >>= 1) v = fmaxf(v, __shfl_xor_sync(0xFFFFFFFFu, v, o));
    return v;
}
__device__ __forceinline__ float wsum(float v) {
    #pragma unroll
    for (int o = 16; o > 0; o >>= 1) v += __shfl_xor_sync(0xFFFFFFFFu, v, o);
    return v;
}

__global__ void __launch_bounds__(256)
softmax_split(const float* __restrict__ SC, __nv_bfloat16* __restrict__ Phi,
              __nv_bfloat16* __restrict__ Plo)
{
    const size_t base = (size_t)blockIdx.x * TP;
    const float* rrow = SC + base;
    const int tid = threadIdx.x, lane = tid & 31, warp = tid >> 5;
    __shared__ float red[8];

    float v[5];
    float mx = -1e30f;
    #pragma unroll
    for (int i = 0; i < 5; i++) {
        int t = tid + i * 256;
        if (t < TT) { float x = rrow[t]; v[i] = x; mx = fmaxf(mx, x); }
        else v[i] = -1e30f;
    }
    mx = wmax(mx);
    if (lane == 0) red[warp] = mx;
    __syncthreads();
    if (warp == 0) {
        float x = (lane < 8) ? red[lane] : -1e30f;
        x = wmax(x);
        if (lane == 0) red[0] = x;
    }
    __syncthreads();
    mx = red[0];
    __syncthreads();

    float sum = 0.0f;
    #pragma unroll
    for (int i = 0; i < 5; i++) {
        int t = tid + i * 256;
        if (t < TT) { float e = expf(v[i] - mx); v[i] = e; sum += e; }
    }
    sum = wsum(sum);
    if (lane == 0) red[warp] = sum;
    __syncthreads();
    if (warp == 0) {
        float x = (lane < 8) ? red[lane] : 0.0f;
        x = wsum(x);
        if (lane == 0) red[0] = x;
    }
    __syncthreads();
    const float inv = 1.0f / red[0];

    #pragma unroll
    for (int i = 0; i < 5; i++) {
        int t = tid + i * 256;
        if (t < TT) {
            float p = v[i] * inv;
            __nv_bfloat16 hh, ll;
            bsplit(p, hh, ll);
            Phi[base + t] = hh;
            Plo[base + t] = ll;
        } else if (t < TP) {
            Phi[base + t] = __float2bfloat16(0.0f);
            Plo[base + t] = __float2bfloat16(0.0f);
        }
    }
}

// ---------------- launch ----------------
extern "C" void kernel_launch(void* const* d_in, const int* in_sizes, int n_in,
                              void* d_out, int out_size)
{
    const float* x    = (const float*)d_in[0];
    const float* mask = (const float*)d_in[1];
    const float* mem  = (const float*)d_in[2];
    const float* wq   = (const float*)d_in[3];
    const float* bq   = (const float*)d_in[4];
    const float* wk   = (const float*)d_in[5];
    const float* bk   = (const float*)d_in[6];
    const float* wv   = (const float*)d_in[7];
    const float* bv   = (const float*)d_in[8];
    const float* wo   = (const float*)d_in[9];
    const float* bo   = (const float*)d_in[10];
    float* out = (float*)d_out;

    __nv_bfloat16 *kvhi, *kvlo, *qhi, *qlo, *khi, *klo, *vthi, *vtlo, *phi, *plo, *hhi, *hlo;
    __nv_bfloat16 (*whi)[(size_t)DD * DD];
    __nv_bfloat16 (*wlo)[(size_t)DD * DD];
    float* sc;
    cudaGetSymbolAddress((void**)&kvhi, g_kvhi);
    cudaGetSymbolAddress((void**)&kvlo, g_kvlo);
    cudaGetSymbolAddress((void**)&qhi,  g_qhi);
    cudaGetSymbolAddress((void**)&qlo,  g_qlo);
    cudaGetSymbolAddress((void**)&khi,  g_khi);
    cudaGetSymbolAddress((void**)&klo,  g_klo);
    cudaGetSymbolAddress((void**)&vthi, g_vthi);
    cudaGetSymbolAddress((void**)&vtlo, g_vtlo);
    cudaGetSymbolAddress((void**)&sc,   g_sc);
    cudaGetSymbolAddress((void**)&phi,  g_phi);
    cudaGetSymbolAddress((void**)&plo,  g_plo);
    cudaGetSymbolAddress((void**)&hhi,  g_hhi);
    cudaGetSymbolAddress((void**)&hlo,  g_hlo);
    cudaGetSymbolAddress((void**)&whi,  g_whi);
    cudaGetSymbolAddress((void**)&wlo,  g_wlo);

    cudaFuncSetAttribute(gemm3, cudaFuncAttributeMaxDynamicSharedMemorySize, GSMEM);

    // 0: concat + split kv input
    {
        int n4 = NKV * (DD / 4);
        build_kv<<<(n4 + 255) / 256, 256>>>((const float4*)x, (const float4*)mem);
    }
    // 1: split all weights
    {
        int tot = 4 * (DD * DD / 4);
        split_all<<<(tot + 255) / 256, 256>>>((const float4*)wq, (const float4*)wk,
                                              (const float4*)wv, (const float4*)wo);
    }

    // 2: Q = x * wq^T + bq  (batched; A rows skip memory tokens)
    gemm3<<<dim3(DD / 128, SS / 128, BB), 256, GSMEM>>>(
        kvhi, kvlo, (long long)TT * DD, DD, SS,
        whi[0], wlo[0], 0, DD, DD,
        DD, 1.0f, bq, 1, nullptr, 0, 0,
        nullptr, qhi, qlo, (long long)SS * DD, DD);

    // 3: K = kv * wk^T + bk
    gemm3<<<dim3(DD / 128, NKV / 128, 1), 256, GSMEM>>>(
        kvhi, kvlo, 0, DD, NKV,
        whi[1], wlo[1], 0, DD, DD,
        DD, 1.0f, bk, 1, nullptr, 0, 0,
        nullptr, khi, klo, 0, DD);

    // 4: Vt[b] = wv * kv[b]^T + bv(rows)   [768 x TP]
    gemm3<<<dim3(TP / 128, DD / 128, BB), 256, GSMEM>>>(
        whi[2], wlo[2], 0, DD, DD,
        kvhi, kvlo, (long long)TT * DD, DD, TT,
        DD, 1.0f, bv, 2, nullptr, 0, 0,
        nullptr, vthi, vtlo, (long long)DD * TP, TP);

    // 5: scores[b] = SCALE * Q[b] K[b]^T + mask -> fp32
    gemm3<<<dim3(TP / 128, SS / 128, BB), 256, GSMEM>>>(
        qhi, qlo, (long long)SS * DD, DD, SS,
        khi, klo, (long long)TT * DD, DD, TT,
        DD, SCALE, nullptr, 0, mask, TT, TT,
        sc, nullptr, nullptr, (long long)SS * TP, TP);

    // 6: softmax -> split P (pad cols zeroed)
    softmax_split<<<NQ, 256>>>(sc, phi, plo);

    // 7: H[b] = P[b] * Vt[b]^T   (K = 1088, pads are exact zeros)
    gemm3<<<dim3(DD / 128, SS / 128, BB), 256, GSMEM>>>(
        phi, plo, (long long)SS * TP, TP, SS,
        vthi, vtlo, (long long)DD * TP, TP, DD,
        KPV, 1.0f, nullptr, 0, nullptr, 0, 0,
        nullptr, hhi, hlo, (long long)SS * DD, DD);

    // 8: out = H * wo^T + bo -> fp32 d_out
    gemm3<<<dim3(DD / 128, NQ / 128, 1), 256, GSMEM>>>(
        hhi, hlo, 0, DD, NQ,
        whi[3], wlo[3], 0, DD, DD,
        DD, 1.0f, bo, 1, nullptr, 0, 0,
        out, nullptr, nullptr, 0, DD);
}

// round 11
// speedup vs baseline: 2.8275x; 1.1763x over previous
#include <cuda_runtime.h>
#include <cuda_bf16.h>
#include <cstdint>
#include <cstddef>

// ---------------- problem constants ----------------
#define DD   768
#define MTOK 16
#define SS   1024
#define BB   16
#define TT   (SS + MTOK)   // 1040
#define TP   1152          // padded kv len (array stride)
#define KPV  1088          // K extent for P*Vt GEMM (17 x 64)
#define NQ   (BB * SS)     // 16384
#define NKV  (BB * TT)     // 16640
#define SCALE 0.036084391824351615f

// ---------------- scratch (device globals) ----------------
__device__ __align__(256) __nv_bfloat16 g_kvhi[(size_t)NKV * DD];
__device__ __align__(256) __nv_bfloat16 g_kvlo[(size_t)NKV * DD];
__device__ __align__(256) __nv_bfloat16 g_qhi [(size_t)NQ  * DD];
__device__ __align__(256) __nv_bfloat16 g_qlo [(size_t)NQ  * DD];
__device__ __align__(256) __nv_bfloat16 g_khi [(size_t)NKV * DD];
__device__ __align__(256) __nv_bfloat16 g_klo [(size_t)NKV * DD];
__device__ __align__(256) __nv_bfloat16 g_vthi[(size_t)BB * DD * TP];
__device__ __align__(256) __nv_bfloat16 g_vtlo[(size_t)BB * DD * TP];
__device__ __align__(256) float         g_sc  [(size_t)BB * SS * TP];
__device__ __align__(256) __nv_bfloat16 g_phi [(size_t)BB * SS * TP];
__device__ __align__(256) __nv_bfloat16 g_plo [(size_t)BB * SS * TP];
__device__ __align__(256) __nv_bfloat16 g_hhi [(size_t)NQ  * DD];
__device__ __align__(256) __nv_bfloat16 g_hlo [(size_t)NQ  * DD];
__device__ __align__(256) __nv_bfloat16 g_whi [4][(size_t)DD * DD];
__device__ __align__(256) __nv_bfloat16 g_wlo [4][(size_t)DD * DD];

// ---------------- helpers ----------------
__device__ __forceinline__ void bsplit(float f, __nv_bfloat16& h, __nv_bfloat16& l) {
    h = __float2bfloat16(f);
    l = __float2bfloat16(f - __bfloat162float(h));
}
__device__ __forceinline__ uint32_t smem_u32(const void* p) {
    uint32_t a;
    asm("{ .reg .u64 t; cvta.to.shared.u64 t, %1; cvt.u32.u64 %0, t; }" : "=r"(a) : "l"(p));
    return a;
}
__device__ __forceinline__ void cp16(uint32_t dst, const void* src) {
    asm volatile("cp.async.cg.shared.global [%0], [%1], 16;" :: "r"(dst), "l"(src));
}
__device__ __forceinline__ void cp_commit() {
    asm volatile("cp.async.commit_group;" ::: "memory");
}
template <int N>
__device__ __forceinline__ void cp_wait() {
    asm volatile("cp.async.wait_group %0;" :: "n"(N) : "memory");
}
__device__ __forceinline__ void ldm4(uint32_t* r, uint32_t addr) {
    asm volatile("ldmatrix.sync.aligned.m8n8.x4.shared.b16 {%0,%1,%2,%3},[%4];"
                 : "=r"(r[0]), "=r"(r[1]), "=r"(r[2]), "=r"(r[3]) : "r"(addr));
}
__device__ __forceinline__ void mma16816(float* c, const uint32_t* a, const uint32_t* b) {
    asm volatile("mma.sync.aligned.m16n8k16.row.col.f32.bf16.bf16.f32 "
                 "{%0,%1,%2,%3},{%4,%5,%6,%7},{%8,%9},{%0,%1,%2,%3};"
                 : "+f"(c[0]), "+f"(c[1]), "+f"(c[2]), "+f"(c[3])
                 : "r"(a[0]), "r"(a[1]), "r"(a[2]), "r"(a[3]), "r"(b[0]), "r"(b[1]));
}

// ---------------- elementwise prep ----------------
__global__ void build_kv(const float4* __restrict__ x, const float4* __restrict__ mem) {
    const int n4 = NKV * (DD / 4);
    int i = blockIdx.x * 256 + threadIdx.x;
    if (i >= n4) return;
    int d4  = i % (DD / 4);
    int row = i / (DD / 4);
    int b = row / TT, t = row % TT;
    float4 v = (t < SS) ? x[(size_t)(b * SS + t) * (DD / 4) + d4]
                        : mem[(size_t)(t - SS) * (DD / 4) + d4];
    union { __nv_bfloat16 bb[4]; uint2 u; } H, L;
    bsplit(v.x, H.bb[0], L.bb[0]);
    bsplit(v.y, H.bb[1], L.bb[1]);
    bsplit(v.z, H.bb[2], L.bb[2]);
    bsplit(v.w, H.bb[3], L.bb[3]);
    ((uint2*)g_kvhi)[i] = H.u;
    ((uint2*)g_kvlo)[i] = L.u;
}

__global__ void split_all(const float4* __restrict__ w0, const float4* __restrict__ w1,
                          const float4* __restrict__ w2, const float4* __restrict__ w3) {
    const int w4 = DD * DD / 4;
    int i = blockIdx.x * 256 + threadIdx.x;
    if (i >= 4 * w4) return;
    int wsel = i / w4;
    int j    = i % w4;
    const float4* src = (wsel == 0) ? w0 : (wsel == 1) ? w1 : (wsel == 2) ? w2 : w3;
    float4 v = src[j];
    union { __nv_bfloat16 bb[4]; uint2 u; } H, L;
    bsplit(v.x, H.bb[0], L.bb[0]);
    bsplit(v.y, H.bb[1], L.bb[1]);
    bsplit(v.z, H.bb[2], L.bb[2]);
    bsplit(v.w, H.bb[3], L.bb[3]);
    ((uint2*)g_whi[wsel])[j] = H.u;
    ((uint2*)g_wlo[wsel])[j] = L.u;
}

// ---------------- HMMA split-bf16 GEMM, BK=64, 512 threads ----------------
// Block 128x128, 16 warps (4x4), warp tile 32x32 -> 4 warps/SMSP.
// 4 matrices per stage: Ahi|Alo|Bhi|Blo, each 128 x 128B, XOR-8 swizzle.
// 3-stage cp.async, one __syncthreads per chunk.

#define MATB  16384                // one matrix tile: 128 x 128B
#define STAGE (4 * MATB)           // 65536
#define GSMEM (3 * STAGE)          // 196608

__global__ void __launch_bounds__(512, 1)
gemm3(const __nv_bfloat16* __restrict__ Ahi, const __nv_bfloat16* __restrict__ Alo,
      long long sA, int ldA, int mrealA,
      const __nv_bfloat16* __restrict__ Bhi, const __nv_bfloat16* __restrict__ Blo,
      long long sB, int ldB, int nrealB,
      int K, float alpha,
      const float* __restrict__ bias, int bias_mode,   // 0 none, 1 over N, 2 over M
      const float* __restrict__ mask, int mask_ld, int mask_n,
      float* __restrict__ Cf, __nv_bfloat16* __restrict__ Chi, __nv_bfloat16* __restrict__ Clo,
      long long sC, int ldC)
{
    extern __shared__ char smem[];
    const uint32_t sb = smem_u32(smem);
    const int tid  = threadIdx.x;
    const int lane = tid & 31;
    const int warp = tid >> 5;
    const int wm = warp >> 2;          // 0..3 (32-row slabs)
    const int wn = warp & 3;           // 0..3 (32-col slabs)

    const int m0 = blockIdx.y * 128, n0 = blockIdx.x * 128;
    const __nv_bfloat16* pAh = Ahi + (size_t)blockIdx.z * sA;
    const __nv_bfloat16* pAl = Alo + (size_t)blockIdx.z * sA;
    const __nv_bfloat16* pBh = Bhi + (size_t)blockIdx.z * sB;
    const __nv_bfloat16* pBl = Blo + (size_t)blockIdx.z * sB;

    // ---- cp.async mapping: 4 threads per row, each covers 32B of the 128B row ----
    const int r = tid >> 2, q = tid & 3;
    int garow = m0 + r; if (garow >= mrealA) garow = mrealA - 1;
    int gbrow = n0 + r; if (gbrow >= nrealB) gbrow = nrealB - 1;
    const __nv_bfloat16* srcAh = pAh + (size_t)garow * ldA + q * 16;
    const __nv_bfloat16* srcAl = pAl + (size_t)garow * ldA + q * 16;
    const __nv_bfloat16* srcBh = pBh + (size_t)gbrow * ldB + q * 16;
    const __nv_bfloat16* srcBl = pBl + (size_t)gbrow * ldB + q * 16;
    uint32_t dstu[2];
    #pragma unroll
    for (int j = 0; j < 2; j++)
        dstu[j] = (uint32_t)r * 128u + (uint32_t)((((q << 1) + j) ^ (r & 7)) * 16);

    const int nchunk = K >> 6;

    auto prefetch = [&](int c, int stg) {
        const uint32_t so = sb + (uint32_t)stg * STAGE;
        const int k0 = c << 6;
        #pragma unroll
        for (int j = 0; j < 2; j++) cp16(so + 0 * MATB + dstu[j], srcAh + k0 + j * 8);
        #pragma unroll
        for (int j = 0; j < 2; j++) cp16(so + 1 * MATB + dstu[j], srcAl + k0 + j * 8);
        #pragma unroll
        for (int j = 0; j < 2; j++) cp16(so + 2 * MATB + dstu[j], srcBh + k0 + j * 8);
        #pragma unroll
        for (int j = 0; j < 2; j++) cp16(so + 3 * MATB + dstu[j], srcBl + k0 + j * 8);
    };

    float acc[2][4][4];
    #pragma unroll
    for (int i = 0; i < 2; i++)
        #pragma unroll
        for (int j = 0; j < 4; j++)
            #pragma unroll
            for (int p = 0; p < 4; p++) acc[i][j][p] = 0.0f;

    const uint32_t band = (uint32_t)(lane & 7);
    const uint32_t a_hi = (uint32_t)(lane >> 4);        // 0/1
    uint32_t arowt[2];
    #pragma unroll
    for (int mt = 0; mt < 2; mt++)
        arowt[mt] = (uint32_t)(wm * 32 + mt * 16 + (lane & 15)) * 128u;
    const uint32_t b_off = (uint32_t)(((lane >> 4) & 1) * 8 + (lane & 7));
    const uint32_t b_hi  = (uint32_t)((lane >> 3) & 1);

    prefetch(0, 0); cp_commit();
    if (nchunk > 1) prefetch(1, 1);
    cp_commit();

    for (int c = 0; c < nchunk; c++) {
        cp_wait<1>();
        __syncthreads();
        if (c + 2 < nchunk) prefetch(c + 2, (c + 2) % 3);
        cp_commit();

        const uint32_t Ab = sb + (uint32_t)(c % 3) * STAGE;
        const uint32_t Bb = Ab + 2 * MATB;

        #pragma unroll
        for (int ks = 0; ks < 4; ks++) {
            uint32_t ah[2][4], al[2][4];
            const uint32_t ua = (uint32_t)(ks * 2) + a_hi;
            #pragma unroll
            for (int mt = 0; mt < 2; mt++) {
                ldm4(ah[mt], Ab + 0 * MATB + arowt[mt] + (ua ^ band) * 16);
                ldm4(al[mt], Ab + 1 * MATB + arowt[mt] + (ua ^ band) * 16);
            }
            const uint32_t ub = (uint32_t)(ks * 2) + b_hi;
            #pragma unroll
            for (int ntp = 0; ntp < 2; ntp++) {
                uint32_t bh[4], bl[4];
                const uint32_t brt = (uint32_t)(wn * 32 + ntp * 16 + b_off) * 128u;
                ldm4(bh, Bb + 0 * MATB + brt + (ub ^ band) * 16);
                ldm4(bl, Bb + 1 * MATB + brt + (ub ^ band) * 16);
                #pragma unroll
                for (int mt = 0; mt < 2; mt++) {
                    mma16816(acc[mt][ntp * 2    ], ah[mt], bh);
                    mma16816(acc[mt][ntp * 2 + 1], ah[mt], bh + 2);
                }
                #pragma unroll
                for (int mt = 0; mt < 2; mt++) {
                    mma16816(acc[mt][ntp * 2    ], ah[mt], bl);
                    mma16816(acc[mt][ntp * 2 + 1], ah[mt], bl + 2);
                }
                #pragma unroll
                for (int mt = 0; mt < 2; mt++) {
                    mma16816(acc[mt][ntp * 2    ], al[mt], bh);
                    mma16816(acc[mt][ntp * 2 + 1], al[mt], bh + 2);
                }
            }
        }
    }

    // ---- epilogue ----
    float* pC = Cf ? (Cf + (size_t)blockIdx.z * sC) : (float*)0;
    __nv_bfloat16* pCh = Chi ? (Chi + (size_t)blockIdx.z * sC) : (__nv_bfloat16*)0;
    __nv_bfloat16* pCl = Clo ? (Clo + (size_t)blockIdx.z * sC) : (__nv_bfloat16*)0;

    #pragma unroll
    for (int mt = 0; mt < 2; mt++) {
        const int row0 = m0 + wm * 32 + mt * 16 + (lane >> 2);
        #pragma unroll
        for (int nt = 0; nt < 4; nt++) {
            const int col = n0 + wn * 32 + nt * 8 + (lane & 3) * 2;
            #pragma unroll
            for (int half = 0; half < 2; half++) {
                const int row = row0 + half * 8;
                float v0 = acc[mt][nt][half * 2    ] * alpha;
                float v1 = acc[mt][nt][half * 2 + 1] * alpha;
                if (bias_mode == 1) {
                    float2 bv = *(const float2*)(bias + col);
                    v0 += bv.x; v1 += bv.y;
                } else if (bias_mode == 2) {
                    float bm = bias[row];
                    v0 += bm; v1 += bm;
                }
                if (mask && col < mask_n) {
                    float2 mv = *(const float2*)(mask + (size_t)row * mask_ld + col);
                    v0 += mv.x; v1 += mv.y;
                }
                if (pC) {
                    float2 ov; ov.x = v0; ov.y = v1;
                    *(float2*)(pC + (size_t)row * ldC + col) = ov;
                } else {
                    __nv_bfloat16 h0, l0, h1, l1;
                    bsplit(v0, h0, l0);
                    bsplit(v1, h1, l1);
                    union { __nv_bfloat16 bb[2]; uint32_t u; } H, L;
                    H.bb[0] = h0; H.bb[1] = h1;
                    L.bb[0] = l0; L.bb[1] = l1;
                    *(uint32_t*)(pCh + (size_t)row * ldC + col) = H.u;
                    *(uint32_t*)(pCl + (size_t)row * ldC + col) = L.u;
                }
            }
        }
    }
}

// ---------------- softmax ----------------
__device__ __forceinline__ float wmax(float v) {
    #pragma unroll
    for (int o = 16; o > 0; o >>= 1) v = fmaxf(v, __shfl_xor_sync(0xFFFFFFFFu, v, o));
    return v;
}
__device__ __forceinline__ float wsum(float v) {
    #pragma unroll
    for (int o = 16; o > 0; o >>= 1) v += __shfl_xor_sync(0xFFFFFFFFu, v, o);
    return v;
}

__global__ void __launch_bounds__(256)
softmax_split(const float* __restrict__ SC, __nv_bfloat16* __restrict__ Phi,
              __nv_bfloat16* __restrict__ Plo)
{
    const size_t base = (size_t)blockIdx.x * TP;
    const float* rrow = SC + base;
    const int tid = threadIdx.x, lane = tid & 31, warp = tid >> 5;
    __shared__ float red[8];

    float v[5];
    float mx = -1e30f;
    #pragma unroll
    for (int i = 0; i < 5; i++) {
        int t = tid + i * 256;
        if (t < TT) { float x = rrow[t]; v[i] = x; mx = fmaxf(mx, x); }
        else v[i] = -1e30f;
    }
    mx = wmax(mx);
    if (lane == 0) red[warp] = mx;
    __syncthreads();
    if (warp == 0) {
        float x = (lane < 8) ? red[lane] : -1e30f;
        x = wmax(x);
        if (lane == 0) red[0] = x;
    }
    __syncthreads();
    mx = red[0];
    __syncthreads();

    float sum = 0.0f;
    #pragma unroll
    for (int i = 0; i < 5; i++) {
        int t = tid + i * 256;
        if (t < TT) { float e = expf(v[i] - mx); v[i] = e; sum += e; }
    }
    sum = wsum(sum);
    if (lane == 0) red[warp] = sum;
    __syncthreads();
    if (warp == 0) {
        float x = (lane < 8) ? red[lane] : 0.0f;
        x = wsum(x);
        if (lane == 0) red[0] = x;
    }
    __syncthreads();
    const float inv = 1.0f / red[0];

    #pragma unroll
    for (int i = 0; i < 5; i++) {
        int t = tid + i * 256;
        if (t < TT) {
            float p = v[i] * inv;
            __nv_bfloat16 hh, ll;
            bsplit(p, hh, ll);
            Phi[base + t] = hh;
            Plo[base + t] = ll;
        } else if (t < TP) {
            Phi[base + t] = __float2bfloat16(0.0f);
            Plo[base + t] = __float2bfloat16(0.0f);
        }
    }
}

// ---------------- launch ----------------
extern "C" void kernel_launch(void* const* d_in, const int* in_sizes, int n_in,
                              void* d_out, int out_size)
{
    const float* x    = (const float*)d_in[0];
    const float* mask = (const float*)d_in[1];
    const float* mem  = (const float*)d_in[2];
    const float* wq   = (const float*)d_in[3];
    const float* bq   = (const float*)d_in[4];
    const float* wk   = (const float*)d_in[5];
    const float* bk   = (const float*)d_in[6];
    const float* wv   = (const float*)d_in[7];
    const float* bv   = (const float*)d_in[8];
    const float* wo   = (const float*)d_in[9];
    const float* bo   = (const float*)d_in[10];
    float* out = (float*)d_out;

    __nv_bfloat16 *kvhi, *kvlo, *qhi, *qlo, *khi, *klo, *vthi, *vtlo, *phi, *plo, *hhi, *hlo;
    __nv_bfloat16 (*whi)[(size_t)DD * DD];
    __nv_bfloat16 (*wlo)[(size_t)DD * DD];
    float* sc;
    cudaGetSymbolAddress((void**)&kvhi, g_kvhi);
    cudaGetSymbolAddress((void**)&kvlo, g_kvlo);
    cudaGetSymbolAddress((void**)&qhi,  g_qhi);
    cudaGetSymbolAddress((void**)&qlo,  g_qlo);
    cudaGetSymbolAddress((void**)&khi,  g_khi);
    cudaGetSymbolAddress((void**)&klo,  g_klo);
    cudaGetSymbolAddress((void**)&vthi, g_vthi);
    cudaGetSymbolAddress((void**)&vtlo, g_vtlo);
    cudaGetSymbolAddress((void**)&sc,   g_sc);
    cudaGetSymbolAddress((void**)&phi,  g_phi);
    cudaGetSymbolAddress((void**)&plo,  g_plo);
    cudaGetSymbolAddress((void**)&hhi,  g_hhi);
    cudaGetSymbolAddress((void**)&hlo,  g_hlo);
    cudaGetSymbolAddress((void**)&whi,  g_whi);
    cudaGetSymbolAddress((void**)&wlo,  g_wlo);

    cudaFuncSetAttribute(gemm3, cudaFuncAttributeMaxDynamicSharedMemorySize, GSMEM);

    // 0: concat + split kv input
    {
        int n4 = NKV * (DD / 4);
        build_kv<<<(n4 + 255) / 256, 256>>>((const float4*)x, (const float4*)mem);
    }
    // 1: split all weights
    {
        int tot = 4 * (DD * DD / 4);
        split_all<<<(tot + 255) / 256, 256>>>((const float4*)wq, (const float4*)wk,
                                              (const float4*)wv, (const float4*)wo);
    }

    // 2: Q = x * wq^T + bq  (batched; A rows skip memory tokens)
    gemm3<<<dim3(DD / 128, SS / 128, BB), 512, GSMEM>>>(
        kvhi, kvlo, (long long)TT * DD, DD, SS,
        whi[0], wlo[0], 0, DD, DD,
        DD, 1.0f, bq, 1, nullptr, 0, 0,
        nullptr, qhi, qlo, (long long)SS * DD, DD);

    // 3: K = kv * wk^T + bk
    gemm3<<<dim3(DD / 128, NKV / 128, 1), 512, GSMEM>>>(
        kvhi, kvlo, 0, DD, NKV,
        whi[1], wlo[1], 0, DD, DD,
        DD, 1.0f, bk, 1, nullptr, 0, 0,
        nullptr, khi, klo, 0, DD);

    // 4: Vt[b] = wv * kv[b]^T + bv(rows)   [768 x TP]
    gemm3<<<dim3(TP / 128, DD / 128, BB), 512, GSMEM>>>(
        whi[2], wlo[2], 0, DD, DD,
        kvhi, kvlo, (long long)TT * DD, DD, TT,
        DD, 1.0f, bv, 2, nullptr, 0, 0,
        nullptr, vthi, vtlo, (long long)DD * TP, TP);

    // 5: scores[b] = SCALE * Q[b] K[b]^T + mask -> fp32
    gemm3<<<dim3(TP / 128, SS / 128, BB), 512, GSMEM>>>(
        qhi, qlo, (long long)SS * DD, DD, SS,
        khi, klo, (long long)TT * DD, DD, TT,
        DD, SCALE, nullptr, 0, mask, TT, TT,
        sc, nullptr, nullptr, (long long)SS * TP, TP);

    // 6: softmax -> split P (pad cols zeroed)
    softmax_split<<<NQ, 256>>>(sc, phi, plo);

    // 7: H[b] = P[b] * Vt[b]^T   (K = 1088, pads are exact zeros)
    gemm3<<<dim3(DD / 128, SS / 128, BB), 512, GSMEM>>>(
        phi, plo, (long long)SS * TP, TP, SS,
        vthi, vtlo, (long long)DD * TP, TP, DD,
        KPV, 1.0f, nullptr, 0, nullptr, 0, 0,
        nullptr, hhi, hlo, (long long)SS * DD, DD);

    // 8: out = H * wo^T + bo -> fp32 d_out
    gemm3<<<dim3(DD / 128, NQ / 128, 1), 512, GSMEM>>>(
        hhi, hlo, 0, DD, NQ,
        whi[3], wlo[3], 0, DD, DD,
        DD, 1.0f, bo, 1, nullptr, 0, 0,
        out, nullptr, nullptr, 0, DD);
}